// round 14
// baseline (speedup 1.0000x reference)
#include <cuda_runtime.h>
#include <cstdint>

#define H 1024
#define L 50
#define V 50257
#define NBLK ((V + 7) / 8)   // 6283 blocks for the big matvec

// ---------------- scratch (device globals; no allocation allowed) ----------
__device__ unsigned g_tc, g_t2;   // exit tickets (comb, out)
__device__ float g_emb[H];
__device__ float g_scores[L];
__device__ float g_cat2[2 * H];   // [embedded | attn_applied]
__device__ float g_cp[4096];      // comb quarter-row partials
__device__ float g_x0[H];         // relu(comb)  = cell-0 input
__device__ float g_h0[H];
__device__ float g_x1[H];         // relu(h1)    = cell-1 input
__device__ float g_h1[H];
__device__ float g_h2[H];
__device__ float g_dp[2 * 6 * H]; // half-row gate partials [half][c][i]
__device__ float g_pm[NBLK + 64];
__device__ float g_ps[NBLK + 64];
__device__ float g_lse;

__device__ __forceinline__ float dot4(float4 a, float4 b) {
    return a.x * b.x + a.y * b.y + a.z * b.z + a.w * b.w;
}
__device__ __forceinline__ float wred(float a) {
    #pragma unroll
    for (int o = 16; o; o >>= 1) a += __shfl_down_sync(0xffffffffu, a, o);
    return a;
}

// ---------------- K-1: reset tickets (graph-replay safe) -------------------
__global__ void k_reset() { g_tc = 0u; g_t2 = 0u; }

// ---------------- K0: attention scores (one block per l) -------------------
__global__ void __launch_bounds__(256)
k_scores(const int* __restrict__ ids,
         const float* __restrict__ hidden,
         const float* __restrict__ emb,
         const float* __restrict__ attn_w,
         const float* __restrict__ attn_b) {
    int l = blockIdx.x;
    int row = ids[0];
    const float* er = emb + (size_t)row * H;

    if (l == 0) {
        for (int i = threadIdx.x; i < H; i += blockDim.x) {
            g_emb[i] = er[i];
            g_h0[i]  = hidden[i];
        }
    }

    const float* w = attn_w + (size_t)l * 2 * H;
    float acc = 0.f;
    for (int j = threadIdx.x; j < H; j += blockDim.x)
        acc += w[j] * er[j] + w[H + j] * hidden[j];

    __shared__ float red[8];
    acc = wred(acc);
    if ((threadIdx.x & 31) == 0) red[threadIdx.x >> 5] = acc;
    __syncthreads();
    if (threadIdx.x < 8) {
        float v = red[threadIdx.x];
        #pragma unroll
        for (int o = 4; o; o >>= 1) v += __shfl_down_sync(0xffu, v, o);
        if (threadIdx.x == 0) g_scores[l] = v + attn_b[l];
    }
}

// ---------------- K1: softmax + attn_applied + concat (8 blocks) -----------
__global__ void __launch_bounds__(128)
k_attn(const float* __restrict__ enc, float* __restrict__ out) {
    __shared__ float aw[64];
    int t = threadIdx.x;
    if (t < 64) aw[t] = (t < L) ? g_scores[t] : -1e30f;
    __syncthreads();
    if (t < 32) {
        float a = aw[t], b = aw[t + 32];
        float m = fmaxf(a, b);
        #pragma unroll
        for (int o = 16; o; o >>= 1) m = fmaxf(m, __shfl_xor_sync(0xffffffffu, m, o));
        float e1 = (t < L) ? __expf(a - m) : 0.f;
        float e2 = (t + 32 < L) ? __expf(b - m) : 0.f;
        float s = e1 + e2;
        #pragma unroll
        for (int o = 16; o; o >>= 1) s += __shfl_xor_sync(0xffffffffu, s, o);
        float inv = 1.f / s;
        aw[t] = e1 * inv;
        aw[t + 32] = e2 * inv;
    }
    __syncthreads();
    if (blockIdx.x == 0 && t < L) out[V + H + t] = aw[t];   // attn_weights
    int i = blockIdx.x * 128 + t;                           // column slice
    float acc = 0.f;
    #pragma unroll 10
    for (int l = 0; l < L; l++) acc += aw[l] * enc[l * H + i];
    g_cat2[H + i] = acc;
    g_cat2[i] = g_emb[i];
}

// ---------------- K2: comb matvec — quarter-row warps, no smem -------------
// 4096 warps / 512 blocks. Front-batched 4x LDG.128 + L1-hot vector reads.
// Exit-ticket: last block computes x0 = relu(sum partials + bias).
__global__ void __launch_bounds__(256)
k_comb(const float* __restrict__ comb_w, const float* __restrict__ comb_b) {
    __shared__ unsigned s_tick;
    int warp = threadIdx.x >> 5, lane = threadIdx.x & 31;
    int u = blockIdx.x * 8 + warp;           // 0..4095
    int row = u >> 2, quar = u & 3;
    const float4* w = (const float4*)(comb_w + (size_t)row * 2 * H) + quar * 128;
    const float4* v = (const float4*)g_cat2 + quar * 128;

    float4 w0 = w[lane], w1 = w[lane + 32], w2 = w[lane + 64], w3 = w[lane + 96];
    float acc = dot4(w0, v[lane]) + dot4(w1, v[lane + 32])
              + dot4(w2, v[lane + 64]) + dot4(w3, v[lane + 96]);
    acc = wred(acc);
    if (lane == 0) g_cp[u] = acc;

    __threadfence();
    __syncthreads();
    if (threadIdx.x == 0) s_tick = atomicAdd(&g_tc, 1u);
    __syncthreads();
    if (s_tick == gridDim.x - 1) {
        for (int i = threadIdx.x; i < H; i += 256) {
            float s = __ldcg(&g_cp[4 * i]) + __ldcg(&g_cp[4 * i + 1])
                    + __ldcg(&g_cp[4 * i + 2]) + __ldcg(&g_cp[4 * i + 3])
                    + comb_b[i];
            g_x0[i] = fmaxf(s, 0.f);
        }
    }
}

// ---------------- K3: GRU gate half-dots — no smem, no barrier -------------
// One warp per (matrix, gate, row, half): 12288 warps / 1536 blocks.
__global__ void __launch_bounds__(256)
k_gates(const float* __restrict__ w_ih, const float* __restrict__ w_hh,
        int cell) {
    int warp = threadIdx.x >> 5, lane = threadIdx.x & 31;
    int id = blockIdx.x * 8 + warp;          // 0..12287
    int half = id & 1;
    int i = (id >> 1) & (H - 1);             // output row
    int c = id >> 11;                        // 0..5
    int gate = c >> 1;
    const float* wmat = (c & 1) ? w_hh : w_ih;
    const float4* w = (const float4*)(wmat + (size_t)(gate * H + i) * H) + half * 128;

    float4 r0 = w[lane];
    float4 r1 = w[lane + 32];
    float4 r2 = w[lane + 64];
    float4 r3 = w[lane + 96];

    const float* vecf = (c & 1) ? ((cell == 0) ? g_h0 : g_h1)
                                : ((cell == 0) ? g_x0 : g_x1);
    const float4* v = (const float4*)vecf + half * 128;
    float acc = dot4(r0, v[lane]) + dot4(r1, v[lane + 32])
              + dot4(r2, v[lane + 64]) + dot4(r3, v[lane + 96]);
    acc = wred(acc);
    if (lane == 0) g_dp[half * 6 * H + c * H + i] = acc;
}

// ---------------- K4: GRU combine: sum halves + biases + nonlinearity ------
__global__ void __launch_bounds__(128)
k_combine(const float* __restrict__ b_ih, const float* __restrict__ b_hh,
          float* __restrict__ out, int cell) {
    int i = blockIdx.x * 128 + threadIdx.x;
    float hold = (cell == 0) ? g_h0[i] : g_h1[i];
    float d[6];
    #pragma unroll
    for (int c = 0; c < 6; c++) {
        float s = g_dp[c * H + i] + g_dp[6 * H + c * H + i];
        int gate = c >> 1;
        s += (c & 1) ? b_hh[gate * H + i] : b_ih[gate * H + i];
        d[c] = s;
    }
    float r = 1.f / (1.f + __expf(-(d[0] + d[1])));
    float z = 1.f / (1.f + __expf(-(d[2] + d[3])));
    float n = tanhf(d[4] + r * d[5]);
    float h = (1.f - z) * n + z * hold;
    if (cell == 0) {
        g_h1[i] = h;
        g_x1[i] = fmaxf(h, 0.f);
    } else {
        g_h2[i] = h;
        out[V + i] = h;                 // hidden output
    }
}

// ---------------- K5: big matvec out_w @ h2 + fused lse --------------------
__global__ void __launch_bounds__(256)
k_out(const float* __restrict__ out_w,
      const float* __restrict__ out_b,
      float* __restrict__ out) {
    __shared__ float sm[8];
    __shared__ unsigned s_tick;
    int warp = threadIdx.x >> 5, lane = threadIdx.x & 31;
    int row = blockIdx.x * 8 + warp;
    float logit = -1e30f;
    if (row < V) {
        const float4* w = (const float4*)(out_w + (size_t)row * H);
        const float4* v = (const float4*)g_h2;
        float acc = 0.f;
        #pragma unroll
        for (int k = 0; k < 8; k++) {
            int m = lane + k * 32;
            float4 a = __ldcs(w + m);   // stream weights
            float4 b = v[m];            // L1-resident vector
            acc += dot4(a, b);
        }
        acc = wred(acc);
        if (lane == 0) {
            logit = acc + out_b[row];
            out[row] = logit;
        }
    }
    if (lane == 0) sm[warp] = logit;
    __syncthreads();
    if (threadIdx.x == 0) {
        float m = -1e30f;
        #pragma unroll
        for (int k = 0; k < 8; k++) m = fmaxf(m, sm[k]);
        float s = 0.f;
        #pragma unroll
        for (int k = 0; k < 8; k++) s += __expf(sm[k] - m);
        g_pm[blockIdx.x] = m;
        g_ps[blockIdx.x] = s;
    }
    __threadfence();
    __syncthreads();
    if (threadIdx.x == 0) s_tick = atomicAdd(&g_t2, 1u);
    __syncthreads();
    if (s_tick == NBLK - 1) {
        int t = threadIdx.x;
        float m = -1e30f, s = 0.f;
        for (int b = t; b < NBLK; b += 256) {
            float bm = __ldcg(&g_pm[b]), bs = __ldcg(&g_ps[b]);
            if (bm > m) { s = s * __expf(m - bm) + bs; m = bm; }
            else        { s += bs * __expf(bm - m); }
        }
        __shared__ float rm[8], rs[8];
        #pragma unroll
        for (int o = 16; o; o >>= 1) {
            float om = __shfl_xor_sync(0xffffffffu, m, o);
            float os = __shfl_xor_sync(0xffffffffu, s, o);
            float M = fmaxf(m, om);
            s = s * __expf(m - M) + os * __expf(om - M);
            m = M;
        }
        if ((t & 31) == 0) { rm[t >> 5] = m; rs[t >> 5] = s; }
        __syncthreads();
        if (t < 8) {
            m = rm[t]; s = rs[t];
            #pragma unroll
            for (int o = 4; o; o >>= 1) {
                float om = __shfl_xor_sync(0xffu, m, o);
                float os = __shfl_xor_sync(0xffu, s, o);
                float M = fmaxf(m, om);
                s = s * __expf(m - M) + os * __expf(om - M);
                m = M;
            }
            if (t == 0) g_lse = m + logf(s);
        }
    }
}

// ---------------- K6: normalize log-probs ----------------------------------
__global__ void __launch_bounds__(256)
k_norm(float* __restrict__ out) {
    int v = blockIdx.x * blockDim.x + threadIdx.x;
    if (v < V) out[v] -= g_lse;
}

// ---------------- launch ----------------------------------------------------
extern "C" void kernel_launch(void* const* d_in, const int* in_sizes, int n_in,
                              void* d_out, int out_size) {
    const int*   ids     = (const int*)d_in[0];
    const float* hidden  = (const float*)d_in[1];
    const float* enc     = (const float*)d_in[2];
    const float* emb     = (const float*)d_in[3];
    const float* attn_w  = (const float*)d_in[4];
    const float* attn_b  = (const float*)d_in[5];
    const float* comb_w  = (const float*)d_in[6];
    const float* comb_b  = (const float*)d_in[7];
    const float* w_ih    = (const float*)d_in[8];
    const float* w_hh    = (const float*)d_in[9];
    const float* b_ih    = (const float*)d_in[10];
    const float* b_hh    = (const float*)d_in[11];
    const float* out_w   = (const float*)d_in[12];
    const float* out_b   = (const float*)d_in[13];
    float* out = (float*)d_out;

    k_reset<<<1, 32>>>();
    k_scores<<<L, 256>>>(ids, hidden, emb, attn_w, attn_b);
    k_attn<<<8, 128>>>(enc, out);
    k_comb<<<512, 256>>>(comb_w, comb_b);
    k_gates<<<1536, 256>>>(w_ih, w_hh, 0);
    k_combine<<<8, 128>>>(b_ih, b_hh, out, 0);
    k_gates<<<1536, 256>>>(w_ih, w_hh, 1);
    k_combine<<<8, 128>>>(b_ih, b_hh, out, 1);
    k_out<<<NBLK, 256>>>(out_w, out_b, out);
    k_norm<<<(V + 255) / 256, 256>>>(out);
}

// round 15
// speedup vs baseline: 1.2602x; 1.2602x over previous
#include <cuda_runtime.h>
#include <cstdint>

#define H 1024
#define L 50
#define V 50257
#define NBLK ((V + 7) / 8)   // 6283 blocks for the big matvec

// ---------------- scratch (device globals; no allocation allowed) ----------
__device__ float g_emb[H];
__device__ float g_scores[L];
__device__ float g_cat2[2 * H];   // [embedded | attn_applied]
__device__ float g_x0[H];         // relu(comb)  = cell-0 input
__device__ float g_h0[H];
__device__ float g_x1[H];         // relu(h1)    = cell-1 input
__device__ float g_h1[H];
__device__ float g_h2[H];
__device__ float g_dp[2 * 6 * H]; // half-row gate partials [half][c][i]
__device__ float g_pm[NBLK + 64];
__device__ float g_ps[NBLK + 64];
__device__ float g_lse;

__device__ __forceinline__ float dot4(float4 a, float4 b) {
    return a.x * b.x + a.y * b.y + a.z * b.z + a.w * b.w;
}
__device__ __forceinline__ float wred(float a) {
    #pragma unroll
    for (int o = 16; o; o >>= 1) a += __shfl_down_sync(0xffffffffu, a, o);
    return a;
}

// ---------------- K0: attention scores (one block per l), plain launch -----
__global__ void __launch_bounds__(256)
k_scores(const int* __restrict__ ids,
         const float* __restrict__ hidden,
         const float* __restrict__ emb,
         const float* __restrict__ attn_w,
         const float* __restrict__ attn_b) {
    cudaTriggerProgrammaticLaunchCompletion();
    int l = blockIdx.x;
    int row = ids[0];
    const float* er = emb + (size_t)row * H;

    if (l == 0) {
        for (int i = threadIdx.x; i < H; i += blockDim.x) {
            g_emb[i] = er[i];
            g_h0[i]  = hidden[i];
        }
    }

    const float* w = attn_w + (size_t)l * 2 * H;
    float acc = 0.f;
    for (int j = threadIdx.x; j < H; j += blockDim.x)
        acc += w[j] * er[j] + w[H + j] * hidden[j];

    __shared__ float red[8];
    acc = wred(acc);
    if ((threadIdx.x & 31) == 0) red[threadIdx.x >> 5] = acc;
    __syncthreads();
    if (threadIdx.x < 8) {
        float v = red[threadIdx.x];
        #pragma unroll
        for (int o = 4; o; o >>= 1) v += __shfl_down_sync(0xffu, v, o);
        if (threadIdx.x == 0) g_scores[l] = v + attn_b[l];
    }
}

// ---------------- K1: softmax + attn_applied + concat (8 blocks, PDL) ------
__global__ void __launch_bounds__(128)
k_attn(const float* __restrict__ enc, float* __restrict__ out) {
    cudaTriggerProgrammaticLaunchCompletion();
    __shared__ float aw[64];
    int t = threadIdx.x;
    cudaGridDependencySynchronize();          // wait for g_scores
    if (t < 64) aw[t] = (t < L) ? g_scores[t] : -1e30f;
    __syncthreads();
    if (t < 32) {
        float a = aw[t], b = aw[t + 32];
        float m = fmaxf(a, b);
        #pragma unroll
        for (int o = 16; o; o >>= 1) m = fmaxf(m, __shfl_xor_sync(0xffffffffu, m, o));
        float e1 = (t < L) ? __expf(a - m) : 0.f;
        float e2 = (t + 32 < L) ? __expf(b - m) : 0.f;
        float s = e1 + e2;
        #pragma unroll
        for (int o = 16; o; o >>= 1) s += __shfl_xor_sync(0xffffffffu, s, o);
        float inv = 1.f / s;
        aw[t] = e1 * inv;
        aw[t + 32] = e2 * inv;
    }
    __syncthreads();
    if (blockIdx.x == 0 && t < L) out[V + H + t] = aw[t];   // attn_weights
    int i = blockIdx.x * 128 + t;                           // column slice
    float acc = 0.f;
    #pragma unroll 10
    for (int l = 0; l < L; l++) acc += aw[l] * enc[l * H + i];
    g_cat2[H + i] = acc;
    g_cat2[i] = g_emb[i];
}

// ---------------- K2: comb matvec (2 warps/row, PDL weight prefetch) -------
__global__ void __launch_bounds__(256)
k_comb(const float* __restrict__ comb_w, const float* __restrict__ comb_b) {
    cudaTriggerProgrammaticLaunchCompletion();
    __shared__ float part[8];
    int warp = threadIdx.x >> 5, lane = threadIdx.x & 31;
    int row = blockIdx.x * 4 + (warp >> 1);
    int half = warp & 1;
    const float4* w = (const float4*)(comb_w + (size_t)row * 2 * H + half * H);

    // independent weight loads overlap the predecessor (k_attn) tail
    float4 w0 = w[lane], w1 = w[lane + 32], w2 = w[lane + 64], w3 = w[lane + 96];
    float4 w4 = w[lane + 128], w5 = w[lane + 160], w6 = w[lane + 192], w7 = w[lane + 224];

    cudaGridDependencySynchronize();          // wait for g_cat2

    const float4* v = (const float4*)(g_cat2 + half * H);
    float acc = dot4(w0, v[lane])       + dot4(w1, v[lane + 32])
              + dot4(w2, v[lane + 64])  + dot4(w3, v[lane + 96])
              + dot4(w4, v[lane + 128]) + dot4(w5, v[lane + 160])
              + dot4(w6, v[lane + 192]) + dot4(w7, v[lane + 224]);
    acc = wred(acc);
    if (lane == 0) part[warp] = acc;
    __syncthreads();
    if (threadIdx.x < 4) {
        int r2 = blockIdx.x * 4 + threadIdx.x;
        float s = part[2 * threadIdx.x] + part[2 * threadIdx.x + 1] + comb_b[r2];
        g_x0[r2] = fmaxf(s, 0.f);
    }
}

// ---------------- K3: GRU gate half-dots (PDL weight prefetch) -------------
// One warp per (matrix, gate, row, half): 12288 warps / 1536 blocks.
__global__ void __launch_bounds__(256)
k_gates(const float* __restrict__ w_ih, const float* __restrict__ w_hh,
        int cell) {
    cudaTriggerProgrammaticLaunchCompletion();
    int warp = threadIdx.x >> 5, lane = threadIdx.x & 31;
    int id = blockIdx.x * 8 + warp;          // 0..12287
    int half = id & 1;
    int i = (id >> 1) & (H - 1);             // output row
    int c = id >> 11;                        // 0..5
    int gate = c >> 1;
    const float* wmat = (c & 1) ? w_hh : w_ih;
    const float4* w = (const float4*)(wmat + (size_t)(gate * H + i) * H) + half * 128;

    // independent weight stream — overlaps predecessor execution
    float4 r0 = w[lane];
    float4 r1 = w[lane + 32];
    float4 r2 = w[lane + 64];
    float4 r3 = w[lane + 96];

    cudaGridDependencySynchronize();          // wait for x/h vectors

    const float* vecf = (c & 1) ? ((cell == 0) ? g_h0 : g_h1)
                                : ((cell == 0) ? g_x0 : g_x1);
    const float4* v = (const float4*)vecf + half * 128;
    float acc = dot4(r0, v[lane]) + dot4(r1, v[lane + 32])
              + dot4(r2, v[lane + 64]) + dot4(r3, v[lane + 96]);
    acc = wred(acc);
    if (lane == 0) g_dp[half * 6 * H + c * H + i] = acc;
}

// ---------------- K4: GRU combine (PDL, bias prefetch) ---------------------
__global__ void __launch_bounds__(128)
k_combine(const float* __restrict__ b_ih, const float* __restrict__ b_hh,
          float* __restrict__ out, int cell) {
    cudaTriggerProgrammaticLaunchCompletion();
    int i = blockIdx.x * 128 + threadIdx.x;
    float bi0 = b_ih[i],         bh0 = b_hh[i];
    float bi1 = b_ih[H + i],     bh1 = b_hh[H + i];
    float bi2 = b_ih[2 * H + i], bh2 = b_hh[2 * H + i];

    cudaGridDependencySynchronize();          // wait for g_dp

    float hold = (cell == 0) ? g_h0[i] : g_h1[i];
    float d0 = g_dp[0 * H + i] + g_dp[6 * H + 0 * H + i] + bi0;
    float d1 = g_dp[1 * H + i] + g_dp[6 * H + 1 * H + i] + bh0;
    float d2 = g_dp[2 * H + i] + g_dp[6 * H + 2 * H + i] + bi1;
    float d3 = g_dp[3 * H + i] + g_dp[6 * H + 3 * H + i] + bh1;
    float d4 = g_dp[4 * H + i] + g_dp[6 * H + 4 * H + i] + bi2;
    float d5 = g_dp[5 * H + i] + g_dp[6 * H + 5 * H + i] + bh2;
    float r = 1.f / (1.f + __expf(-(d0 + d1)));
    float z = 1.f / (1.f + __expf(-(d2 + d3)));
    float n = tanhf(d4 + r * d5);
    float h = (1.f - z) * n + z * hold;
    if (cell == 0) {
        g_h1[i] = h;
        g_x1[i] = fmaxf(h, 0.f);
    } else {
        g_h2[i] = h;
        out[V + i] = h;                 // hidden output
    }
}

// ---------------- K5: big matvec out_w @ h2 (R10 body, PDL-gated) ----------
__global__ void __launch_bounds__(256)
k_out(const float* __restrict__ out_w,
      const float* __restrict__ out_b,
      float* __restrict__ out) {
    cudaTriggerProgrammaticLaunchCompletion();
    cudaGridDependencySynchronize();          // wait for g_h2
    __shared__ float sm[8];
    int warp = threadIdx.x >> 5, lane = threadIdx.x & 31;
    int row = blockIdx.x * 8 + warp;
    float logit = -1e30f;
    if (row < V) {
        const float4* w = (const float4*)(out_w + (size_t)row * H);
        const float4* v = (const float4*)g_h2;
        float acc = 0.f;
        #pragma unroll
        for (int k = 0; k < 8; k++) {
            int m = lane + k * 32;
            float4 a = __ldcs(w + m);   // stream weights
            float4 b = v[m];            // L1-resident vector
            acc += dot4(a, b);
        }
        acc = wred(acc);
        if (lane == 0) {
            logit = acc + out_b[row];
            out[row] = logit;
        }
    }
    if (lane == 0) sm[warp] = logit;
    __syncthreads();
    if (threadIdx.x == 0) {
        float m = -1e30f;
        #pragma unroll
        for (int k = 0; k < 8; k++) m = fmaxf(m, sm[k]);
        float s = 0.f;
        #pragma unroll
        for (int k = 0; k < 8; k++) s += __expf(sm[k] - m);
        g_pm[blockIdx.x] = m;
        g_ps[blockIdx.x] = s;
    }
}

// ---------------- K6: combine partials -> lse (PDL) ------------------------
__global__ void __launch_bounds__(256)
k_lse() {
    cudaTriggerProgrammaticLaunchCompletion();
    cudaGridDependencySynchronize();
    int t = threadIdx.x;
    float m = -1e30f, s = 0.f;
    for (int b = t; b < NBLK; b += 256) {
        float bm = g_pm[b], bs = g_ps[b];
        if (bm > m) { s = s * __expf(m - bm) + bs; m = bm; }
        else        { s += bs * __expf(bm - m); }
    }
    __shared__ float rm[8], rs[8];
    #pragma unroll
    for (int o = 16; o; o >>= 1) {
        float om = __shfl_xor_sync(0xffffffffu, m, o);
        float os = __shfl_xor_sync(0xffffffffu, s, o);
        float M = fmaxf(m, om);
        s = s * __expf(m - M) + os * __expf(om - M);
        m = M;
    }
    if ((t & 31) == 0) { rm[t >> 5] = m; rs[t >> 5] = s; }
    __syncthreads();
    if (t < 8) {
        m = rm[t]; s = rs[t];
        #pragma unroll
        for (int o = 4; o; o >>= 1) {
            float om = __shfl_xor_sync(0xffu, m, o);
            float os = __shfl_xor_sync(0xffu, s, o);
            float M = fmaxf(m, om);
            s = s * __expf(m - M) + os * __expf(om - M);
            m = M;
        }
        if (t == 0) g_lse = m + logf(s);
    }
}

// ---------------- K7: normalize log-probs (PDL) ----------------------------
__global__ void __launch_bounds__(256)
k_norm(float* __restrict__ out) {
    cudaGridDependencySynchronize();
    int v = blockIdx.x * blockDim.x + threadIdx.x;
    if (v < V) out[v] -= g_lse;
}

// ---------------- launch ----------------------------------------------------
template <typename F, typename... Args>
static void pdl(F f, dim3 grid, dim3 block, Args... args) {
    cudaLaunchConfig_t cfg = {};
    cfg.gridDim = grid;
    cfg.blockDim = block;
    cfg.stream = 0;
    cudaLaunchAttribute at[1];
    at[0].id = cudaLaunchAttributeProgrammaticStreamSerialization;
    at[0].val.programmaticStreamSerializationAllowed = 1;
    cfg.attrs = at;
    cfg.numAttrs = 1;
    cudaLaunchKernelEx(&cfg, f, args...);
}

extern "C" void kernel_launch(void* const* d_in, const int* in_sizes, int n_in,
                              void* d_out, int out_size) {
    const int*   ids     = (const int*)d_in[0];
    const float* hidden  = (const float*)d_in[1];
    const float* enc     = (const float*)d_in[2];
    const float* emb     = (const float*)d_in[3];
    const float* attn_w  = (const float*)d_in[4];
    const float* attn_b  = (const float*)d_in[5];
    const float* comb_w  = (const float*)d_in[6];
    const float* comb_b  = (const float*)d_in[7];
    const float* w_ih    = (const float*)d_in[8];
    const float* w_hh    = (const float*)d_in[9];
    const float* b_ih    = (const float*)d_in[10];
    const float* b_hh    = (const float*)d_in[11];
    const float* out_w   = (const float*)d_in[12];
    const float* out_b   = (const float*)d_in[13];
    float* out = (float*)d_out;

    k_scores<<<L, 256>>>(ids, hidden, emb, attn_w, attn_b);
    pdl(k_attn, dim3(8), dim3(128), enc, out);
    pdl(k_comb, dim3(256), dim3(256), comb_w, comb_b);
    pdl(k_gates, dim3(1536), dim3(256), w_ih, w_hh, 0);
    pdl(k_combine, dim3(8), dim3(128), b_ih, b_hh, out, 0);
    pdl(k_gates, dim3(1536), dim3(256), w_ih, w_hh, 1);
    pdl(k_combine, dim3(8), dim3(128), b_ih, b_hh, out, 1);
    pdl(k_out, dim3(NBLK), dim3(256), out_w, out_b, out);
    pdl(k_lse, dim3(1), dim3(256));
    pdl(k_norm, dim3((V + 255) / 256), dim3(256), out);
}

// round 16
// speedup vs baseline: 1.3097x; 1.0393x over previous
#include <cuda_runtime.h>
#include <cstdint>

#define H 1024
#define L 50
#define V 50257
#define NBLK ((V + 7) / 8)   // 6283 blocks for the big matvec

// ---------------- scratch (device globals; no allocation allowed) ----------
__device__ float g_emb[H];
__device__ float g_scores[L];
__device__ float g_cat2[2 * H];   // [embedded | attn_applied]
__device__ float g_x0[H];         // relu(comb)  = cell-0 input
__device__ float g_h0[H];
__device__ float g_x1[H];         // relu(h1)    = cell-1 input
__device__ float g_h1[H];
__device__ float g_h2[H];
__device__ float g_dp[2 * 6 * H]; // half-row gate partials [half][c][i]
__device__ float g_pm[NBLK + 64];
__device__ float g_ps[NBLK + 64];
__device__ float g_lse;

__device__ __forceinline__ float dot4(float4 a, float4 b) {
    return a.x * b.x + a.y * b.y + a.z * b.z + a.w * b.w;
}
__device__ __forceinline__ float wred(float a) {
    #pragma unroll
    for (int o = 16; o; o >>= 1) a += __shfl_down_sync(0xffffffffu, a, o);
    return a;
}

// ---------------- K0: attention scores (one block per l), plain launch -----
__global__ void __launch_bounds__(256)
k_scores(const int* __restrict__ ids,
         const float* __restrict__ hidden,
         const float* __restrict__ emb,
         const float* __restrict__ attn_w,
         const float* __restrict__ attn_b) {
    cudaTriggerProgrammaticLaunchCompletion();
    int l = blockIdx.x;
    int row = ids[0];
    const float* er = emb + (size_t)row * H;

    if (l == 0) {
        for (int i = threadIdx.x; i < H; i += blockDim.x) {
            g_emb[i] = er[i];
            g_h0[i]  = hidden[i];
        }
    }

    const float* w = attn_w + (size_t)l * 2 * H;
    float acc = 0.f;
    for (int j = threadIdx.x; j < H; j += blockDim.x)
        acc += w[j] * er[j] + w[H + j] * hidden[j];

    __shared__ float red[8];
    acc = wred(acc);
    if ((threadIdx.x & 31) == 0) red[threadIdx.x >> 5] = acc;
    __syncthreads();
    if (threadIdx.x < 8) {
        float v = red[threadIdx.x];
        #pragma unroll
        for (int o = 4; o; o >>= 1) v += __shfl_down_sync(0xffu, v, o);
        if (threadIdx.x == 0) g_scores[l] = v + attn_b[l];
    }
}

// ---------------- K1: softmax + attn_applied + concat (8 blocks, PDL) ------
__global__ void __launch_bounds__(128)
k_attn(const float* __restrict__ enc, float* __restrict__ out) {
    __shared__ float aw[64];
    int t = threadIdx.x;
    cudaGridDependencySynchronize();          // wait for g_scores
    cudaTriggerProgrammaticLaunchCompletion();// invariant: trigger after sync
    if (t < 64) aw[t] = (t < L) ? g_scores[t] : -1e30f;
    __syncthreads();
    if (t < 32) {
        float a = aw[t], b = aw[t + 32];
        float m = fmaxf(a, b);
        #pragma unroll
        for (int o = 16; o; o >>= 1) m = fmaxf(m, __shfl_xor_sync(0xffffffffu, m, o));
        float e1 = (t < L) ? __expf(a - m) : 0.f;
        float e2 = (t + 32 < L) ? __expf(b - m) : 0.f;
        float s = e1 + e2;
        #pragma unroll
        for (int o = 16; o; o >>= 1) s += __shfl_xor_sync(0xffffffffu, s, o);
        float inv = 1.f / s;
        aw[t] = e1 * inv;
        aw[t + 32] = e2 * inv;
    }
    __syncthreads();
    if (blockIdx.x == 0 && t < L) out[V + H + t] = aw[t];   // attn_weights
    int i = blockIdx.x * 128 + t;                           // column slice
    float acc = 0.f;
    #pragma unroll 10
    for (int l = 0; l < L; l++) acc += aw[l] * enc[l * H + i];
    g_cat2[H + i] = acc;
    g_cat2[i] = g_emb[i];
}

// ---------------- K2: comb matvec (2 warps/row, PDL weight prefetch) -------
__global__ void __launch_bounds__(256)
k_comb(const float* __restrict__ comb_w, const float* __restrict__ comb_b) {
    __shared__ float part[8];
    int warp = threadIdx.x >> 5, lane = threadIdx.x & 31;
    int row = blockIdx.x * 4 + (warp >> 1);
    int half = warp & 1;
    const float4* w = (const float4*)(comb_w + (size_t)row * 2 * H + half * H);

    // independent weight loads overlap the predecessor (k_attn)
    float4 w0 = w[lane], w1 = w[lane + 32], w2 = w[lane + 64], w3 = w[lane + 96];
    float4 w4 = w[lane + 128], w5 = w[lane + 160], w6 = w[lane + 192], w7 = w[lane + 224];

    cudaGridDependencySynchronize();          // wait for g_cat2
    cudaTriggerProgrammaticLaunchCompletion();

    const float4* v = (const float4*)(g_cat2 + half * H);
    float acc = dot4(w0, v[lane])       + dot4(w1, v[lane + 32])
              + dot4(w2, v[lane + 64])  + dot4(w3, v[lane + 96])
              + dot4(w4, v[lane + 128]) + dot4(w5, v[lane + 160])
              + dot4(w6, v[lane + 192]) + dot4(w7, v[lane + 224]);
    acc = wred(acc);
    if (lane == 0) part[warp] = acc;
    __syncthreads();
    if (threadIdx.x < 4) {
        int r2 = blockIdx.x * 4 + threadIdx.x;
        float s = part[2 * threadIdx.x] + part[2 * threadIdx.x + 1] + comb_b[r2];
        g_x0[r2] = fmaxf(s, 0.f);
    }
}

// ---------------- K3: GRU gate half-dots (PDL, deep overlap) ---------------
// One warp per (matrix, gate, row, half): 12288 warps / 1536 blocks.
// cell 0: the hh-side dots depend only on g_h0 (complete since k_scores, by
// the trigger-after-sync chain invariant) -> computed ENTIRELY pre-gridsync,
// overlapping k_comb. Only the ih-side (needs g_x0) waits.
__global__ void __launch_bounds__(256)
k_gates(const float* __restrict__ w_ih, const float* __restrict__ w_hh,
        int cell) {
    int warp = threadIdx.x >> 5, lane = threadIdx.x & 31;
    int id = blockIdx.x * 8 + warp;          // 0..12287
    int half = id & 1;
    int i = (id >> 1) & (H - 1);             // output row
    int c = id >> 11;                        // 0..5 (warp-uniform)
    int gate = c >> 1;
    bool hside = (c & 1);
    const float* wmat = hside ? w_hh : w_ih;
    const float4* w = (const float4*)(wmat + (size_t)(gate * H + i) * H) + half * 128;

    // independent weight stream — overlaps predecessor execution
    float4 r0 = w[lane];
    float4 r1 = w[lane + 32];
    float4 r2 = w[lane + 64];
    float4 r3 = w[lane + 96];

    float acc = 0.f;
    bool pre = (cell == 0) && hside;         // safe: g_h0 complete (invariant)
    if (pre) {
        const float4* v = (const float4*)g_h0 + half * 128;
        acc = dot4(r0, v[lane]) + dot4(r1, v[lane + 32])
            + dot4(r2, v[lane + 64]) + dot4(r3, v[lane + 96]);
    }

    cudaGridDependencySynchronize();          // wait for x/h vectors
    cudaTriggerProgrammaticLaunchCompletion();

    if (!pre) {
        const float* vecf = hside ? g_h1
                                  : ((cell == 0) ? g_x0 : g_x1);
        const float4* v = (const float4*)vecf + half * 128;
        acc = dot4(r0, v[lane]) + dot4(r1, v[lane + 32])
            + dot4(r2, v[lane + 64]) + dot4(r3, v[lane + 96]);
    }
    acc = wred(acc);
    if (lane == 0) g_dp[half * 6 * H + c * H + i] = acc;
}

// ---------------- K4: GRU combine (PDL, bias prefetch) ---------------------
__global__ void __launch_bounds__(128)
k_combine(const float* __restrict__ b_ih, const float* __restrict__ b_hh,
          float* __restrict__ out, int cell) {
    int i = blockIdx.x * 128 + threadIdx.x;
    float bi0 = b_ih[i],         bh0 = b_hh[i];
    float bi1 = b_ih[H + i],     bh1 = b_hh[H + i];
    float bi2 = b_ih[2 * H + i], bh2 = b_hh[2 * H + i];

    cudaGridDependencySynchronize();          // wait for g_dp
    cudaTriggerProgrammaticLaunchCompletion();

    float hold = (cell == 0) ? g_h0[i] : g_h1[i];
    float d0 = g_dp[0 * H + i] + g_dp[6 * H + 0 * H + i] + bi0;
    float d1 = g_dp[1 * H + i] + g_dp[6 * H + 1 * H + i] + bh0;
    float d2 = g_dp[2 * H + i] + g_dp[6 * H + 2 * H + i] + bi1;
    float d3 = g_dp[3 * H + i] + g_dp[6 * H + 3 * H + i] + bh1;
    float d4 = g_dp[4 * H + i] + g_dp[6 * H + 4 * H + i] + bi2;
    float d5 = g_dp[5 * H + i] + g_dp[6 * H + 5 * H + i] + bh2;
    float r = 1.f / (1.f + __expf(-(d0 + d1)));
    float z = 1.f / (1.f + __expf(-(d2 + d3)));
    float n = tanhf(d4 + r * d5);
    float h = (1.f - z) * n + z * hold;
    if (cell == 0) {
        g_h1[i] = h;
        g_x1[i] = fmaxf(h, 0.f);
    } else {
        g_h2[i] = h;
        out[V + i] = h;                 // hidden output
    }
}

// ---------------- K5: big matvec out_w @ h2 (PDL weight prefetch) ----------
__global__ void __launch_bounds__(256)
k_out(const float* __restrict__ out_w,
      const float* __restrict__ out_b,
      float* __restrict__ out) {
    __shared__ float sm[8];
    int warp = threadIdx.x >> 5, lane = threadIdx.x & 31;
    int row = blockIdx.x * 8 + warp;
    bool valid = (row < V);
    const float4* w = (const float4*)(out_w + (size_t)(valid ? row : 0) * H);

    // start the 206 MB weight stream BEFORE waiting on the GRU tail
    float4 a0 = __ldcs(w + lane),       a1 = __ldcs(w + lane + 32);
    float4 a2 = __ldcs(w + lane + 64),  a3 = __ldcs(w + lane + 96);
    float4 a4 = __ldcs(w + lane + 128), a5 = __ldcs(w + lane + 160);
    float4 a6 = __ldcs(w + lane + 192), a7 = __ldcs(w + lane + 224);

    cudaGridDependencySynchronize();          // wait for g_h2
    cudaTriggerProgrammaticLaunchCompletion();

    float logit = -1e30f;
    const float4* v = (const float4*)g_h2;
    float acc = dot4(a0, v[lane])       + dot4(a1, v[lane + 32])
              + dot4(a2, v[lane + 64])  + dot4(a3, v[lane + 96])
              + dot4(a4, v[lane + 128]) + dot4(a5, v[lane + 160])
              + dot4(a6, v[lane + 192]) + dot4(a7, v[lane + 224]);
    acc = wred(acc);
    if (lane == 0 && valid) {
        logit = acc + out_b[row];
        out[row] = logit;
    }
    if (lane == 0) sm[warp] = logit;
    __syncthreads();
    if (threadIdx.x == 0) {
        float m = -1e30f;
        #pragma unroll
        for (int k = 0; k < 8; k++) m = fmaxf(m, sm[k]);
        float s = 0.f;
        #pragma unroll
        for (int k = 0; k < 8; k++) s += __expf(sm[k] - m);
        g_pm[blockIdx.x] = m;
        g_ps[blockIdx.x] = s;
    }
}

// ---------------- K6: combine partials -> lse (PDL) ------------------------
__global__ void __launch_bounds__(256)
k_lse() {
    cudaGridDependencySynchronize();
    cudaTriggerProgrammaticLaunchCompletion();
    int t = threadIdx.x;
    float m = -1e30f, s = 0.f;
    for (int b = t; b < NBLK; b += 256) {
        float bm = g_pm[b], bs = g_ps[b];
        if (bm > m) { s = s * __expf(m - bm) + bs; m = bm; }
        else        { s += bs * __expf(bm - m); }
    }
    __shared__ float rm[8], rs[8];
    #pragma unroll
    for (int o = 16; o; o >>= 1) {
        float om = __shfl_xor_sync(0xffffffffu, m, o);
        float os = __shfl_xor_sync(0xffffffffu, s, o);
        float M = fmaxf(m, om);
        s = s * __expf(m - M) + os * __expf(om - M);
        m = M;
    }
    if ((t & 31) == 0) { rm[t >> 5] = m; rs[t >> 5] = s; }
    __syncthreads();
    if (t < 8) {
        m = rm[t]; s = rs[t];
        #pragma unroll
        for (int o = 4; o; o >>= 1) {
            float om = __shfl_xor_sync(0xffu, m, o);
            float os = __shfl_xor_sync(0xffu, s, o);
            float M = fmaxf(m, om);
            s = s * __expf(m - M) + os * __expf(om - M);
            m = M;
        }
        if (t == 0) g_lse = m + logf(s);
    }
}

// ---------------- K7: normalize log-probs (PDL) ----------------------------
__global__ void __launch_bounds__(256)
k_norm(float* __restrict__ out) {
    cudaGridDependencySynchronize();
    int v = blockIdx.x * blockDim.x + threadIdx.x;
    if (v < V) out[v] -= g_lse;
}

// ---------------- launch ----------------------------------------------------
template <typename F, typename... Args>
static void pdl(F f, dim3 grid, dim3 block, Args... args) {
    cudaLaunchConfig_t cfg = {};
    cfg.gridDim = grid;
    cfg.blockDim = block;
    cfg.stream = 0;
    cudaLaunchAttribute at[1];
    at[0].id = cudaLaunchAttributeProgrammaticStreamSerialization;
    at[0].val.programmaticStreamSerializationAllowed = 1;
    cfg.attrs = at;
    cfg.numAttrs = 1;
    cudaLaunchKernelEx(&cfg, f, args...);
}

extern "C" void kernel_launch(void* const* d_in, const int* in_sizes, int n_in,
                              void* d_out, int out_size) {
    const int*   ids     = (const int*)d_in[0];
    const float* hidden  = (const float*)d_in[1];
    const float* enc     = (const float*)d_in[2];
    const float* emb     = (const float*)d_in[3];
    const float* attn_w  = (const float*)d_in[4];
    const float* attn_b  = (const float*)d_in[5];
    const float* comb_w  = (const float*)d_in[6];
    const float* comb_b  = (const float*)d_in[7];
    const float* w_ih    = (const float*)d_in[8];
    const float* w_hh    = (const float*)d_in[9];
    const float* b_ih    = (const float*)d_in[10];
    const float* b_hh    = (const float*)d_in[11];
    const float* out_w   = (const float*)d_in[12];
    const float* out_b   = (const float*)d_in[13];
    float* out = (float*)d_out;

    k_scores<<<L, 256>>>(ids, hidden, emb, attn_w, attn_b);
    pdl(k_attn, dim3(8), dim3(128), enc, out);
    pdl(k_comb, dim3(256), dim3(256), comb_w, comb_b);
    pdl(k_gates, dim3(1536), dim3(256), w_ih, w_hh, 0);
    pdl(k_combine, dim3(8), dim3(128), b_ih, b_hh, out, 0);
    pdl(k_gates, dim3(1536), dim3(256), w_ih, w_hh, 1);
    pdl(k_combine, dim3(8), dim3(128), b_ih, b_hh, out, 1);
    pdl(k_out, dim3(NBLK), dim3(256), out_w, out_b, out);
    pdl(k_lse, dim3(1), dim3(256));
    pdl(k_norm, dim3((V + 255) / 256), dim3(256), out);
}